// round 1
// baseline (speedup 1.0000x reference)
#include <cuda_runtime.h>
#include <cuda_bf16.h>
#include <math.h>

// ---------------- problem constants ----------------
#define BB    16
#define AT    96
#define NBRN  12
#define M_ROWS 18432      /* BB*AT*NBRN */
#define BA_ROWS 1536      /* BB*AT */
#define F1    128         /* Fn+Fe */
#define H1    512
#define H2    128
#define FN    64
#define K1    1024        /* 8 planes * F1 */
#define K2    4096        /* 8 planes * H1 */

// ---------------- scratch (static device globals; no runtime alloc) ----------------
__device__ float          g_c1[M_ROWS * F1];                    // 9.4 MB
__device__ __nv_bfloat16  g_A1[M_ROWS * K1];                    // 37.7 MB
__device__ __nv_bfloat16  g_A2[(size_t)M_ROWS * K2];            // 151 MB
__device__ __nv_bfloat16  g_W1hi[H1 * K1];
__device__ __nv_bfloat16  g_W1lo[H1 * K1];
__device__ __nv_bfloat16  g_W2hi[H2 * K2];
__device__ __nv_bfloat16  g_W2lo[H2 * K2];
__device__ float          g_S1[H1];
__device__ float          g_S2[H2];
__device__ float          g_h[(size_t)M_ROWS * H1];             // 37.7 MB
__device__ float          g_c2[M_ROWS * H2];                    // 9.4 MB
__device__ float          g_ns[BA_ROWS * FN];
__device__ float          g_mean[FN], g_var[FN];
__device__ int            g_mn1, g_mx1, g_mn2, g_mx2;           // float bits

// ---------------- helpers ----------------
__device__ __forceinline__ void atomicMinF(int* a, float v) {
    if (v >= 0.f) atomicMin(a, __float_as_int(v));
    else          atomicMax((unsigned int*)a, (unsigned int)__float_as_int(v));
}
__device__ __forceinline__ void atomicMaxF(int* a, float v) {
    if (v >= 0.f) atomicMax(a, __float_as_int(v));
    else          atomicMin((unsigned int*)a, (unsigned int)__float_as_int(v));
}
__device__ __forceinline__ void cp_async16(void* s, const void* g) {
    unsigned sa = (unsigned)__cvta_generic_to_shared(s);
    asm volatile("cp.async.cg.shared.global [%0], [%1], 16;\n" :: "r"(sa), "l"(g));
}

// ---------------- kernels ----------------
__global__ void k_init() {
    g_mn1 = 0x7f800000; g_mx1 = (int)0xff800000;
    g_mn2 = 0x7f800000; g_mx2 = (int)0xff800000;
}

// build c1 = concat(node bcast, edge) and global min/max
__global__ void k_c1(const float* __restrict__ node, const float* __restrict__ edge) {
    int idx = blockIdx.x * 256 + threadIdx.x;       // < M_ROWS*F1
    int m = idx >> 7, j = idx & 127;
    float v = (j < FN) ? node[(m / NBRN) * FN + j] : edge[m * 64 + (j - 64)];
    g_c1[idx] = v;
    float mn = v, mx = v;
    #pragma unroll
    for (int o = 16; o; o >>= 1) {
        mn = fminf(mn, __shfl_xor_sync(0xffffffffu, mn, o));
        mx = fmaxf(mx, __shfl_xor_sync(0xffffffffu, mx, o));
    }
    __shared__ float smn[8], smx[8];
    int lane = threadIdx.x & 31, w = threadIdx.x >> 5;
    if (lane == 0) { smn[w] = mn; smx[w] = mx; }
    __syncthreads();
    if (threadIdx.x == 0) {
        float bmn = smn[0], bmx = smx[0];
        #pragma unroll
        for (int i = 1; i < 8; i++) { bmn = fminf(bmn, smn[i]); bmx = fmaxf(bmx, smx[i]); }
        atomicMinF(&g_mn1, bmn); atomicMaxF(&g_mx1, bmx);
    }
}

// layer-1 effective weights: Weff[k=(b,i)][o] = 2^b * (w + eps*|w|*0.1), hi/lo bf16 split
// S1[o] = sum_i w_noisy[7,o,i] (for bias1 = mn1 * S1)
__global__ void k_prep1(const float* __restrict__ cond1, const float* __restrict__ eps1) {
    int o = blockIdx.x, i = threadIdx.x;            // 512 blocks x 128 threads
    float w = cond1[o * F1 + i];
    float aw = fabsf(w) * 0.1f;
    float s7 = 0.f;
    #pragma unroll
    for (int b = 0; b < 8; b++) {
        float wn = w + eps1[b * (H1 * F1) + o * F1 + i] * aw;
        if (b == 7) s7 = wn;
        float v = wn * (float)(1 << b);
        __nv_bfloat16 hi = __float2bfloat16(v);
        float lo = v - __bfloat162float(hi);
        g_W1hi[o * K1 + b * F1 + i] = hi;
        g_W1lo[o * K1 + b * F1 + i] = __float2bfloat16(lo);
    }
    __shared__ float red[128];
    red[i] = s7; __syncthreads();
    #pragma unroll
    for (int s = 64; s; s >>= 1) { if (i < s) red[i] += red[i + s]; __syncthreads(); }
    if (i == 0) g_S1[o] = red[0];
}

// layer-2 weights; S2[o] = sum_k cond2[1][o][k] (RAW second slice per reference)
__global__ void k_prep2(const float* __restrict__ cond2, const float* __restrict__ eps2) {
    int o = blockIdx.x, t = threadIdx.x;            // 128 blocks x 256 threads
    float sr = 0.f;
    for (int i = t; i < H1; i += 256) {
        float w = cond2[o * H1 + i];
        float aw = fabsf(w) * 0.1f;
        sr += cond2[H2 * H1 + o * H1 + i];
        #pragma unroll
        for (int b = 0; b < 8; b++) {
            float wn = w + eps2[b * (H2 * H1) + o * H1 + i] * aw;
            float v = wn * (float)(1 << b);
            __nv_bfloat16 hi = __float2bfloat16(v);
            float lo = v - __bfloat162float(hi);
            g_W2hi[o * K2 + b * H1 + i] = hi;
            g_W2lo[o * K2 + b * H1 + i] = __float2bfloat16(lo);
        }
    }
    __shared__ float red[256];
    red[t] = sr; __syncthreads();
    #pragma unroll
    for (int s = 128; s; s >>= 1) { if (t < s) red[t] += red[t + s]; __syncthreads(); }
    if (t == 0) g_S2[o] = red[0];
}

// expand layer-1 bit planes: A1[m][b*F1+i] = bit_b(q1[m,i]) (binary, exact in bf16)
__global__ void k_bits1() {
    int idx = blockIdx.x * 256 + threadIdx.x;       // < M_ROWS*K1
    int m = idx >> 10, k = idx & 1023;
    int b = k >> 7, i = k & 127;
    float mn = __int_as_float(g_mn1), mx = __int_as_float(g_mx1);
    float x = g_c1[m * F1 + i];
    float t = (x - mn) / (mx - mn) * 255.0f;
    int q = (int)t; q = q < 0 ? 0 : (q > 255 ? 255 : q);
    ((unsigned short*)g_A1)[idx] = ((q >> b) & 1) ? 0x3F80 : 0;
}

__global__ void k_bits2() {
    size_t idx = (size_t)blockIdx.x * 256 + threadIdx.x;  // < M_ROWS*K2
    int m = (int)(idx >> 12); int k = (int)(idx & 4095);
    int b = k >> 9, i = k & 511;
    float mn = __int_as_float(g_mn2), mx = __int_as_float(g_mx2);
    float x = g_h[(size_t)m * H1 + i];
    float t = (x - mn) / (mx - mn) * 255.0f;
    int q = (int)t; q = q < 0 ? 0 : (q > 255 ? 255 : q);
    ((unsigned short*)g_A2)[idx] = ((q >> b) & 1) ? 0x3F80 : 0;
}

// ---------------- GEMM: C[M,N] = A[M,K] @ (Whi + Wlo)[N,K]^T, fused epilogue ----------------
// CTA tile 128x128, BK=64, 8 warps (4x2), warp tile 32x64, mma.sync m16n8k16 bf16->fp32.
template<int EPI>
__global__ void __launch_bounds__(256, 2) k_gemm() {
    constexpr int K  = (EPI == 1) ? K1 : K2;
    constexpr int N  = (EPI == 1) ? H1 : H2;
    constexpr int KT = K / 64;
    const __nv_bfloat16* A   = (EPI == 1) ? g_A1   : g_A2;
    const __nv_bfloat16* Whi = (EPI == 1) ? g_W1hi : g_W2hi;
    const __nv_bfloat16* Wlo = (EPI == 1) ? g_W1lo : g_W2lo;
    const float*         S   = (EPI == 1) ? g_S1   : g_S2;
    float*               out = (EPI == 1) ? g_h    : g_c2;

    extern __shared__ __nv_bfloat16 smbuf[];
    constexpr int SROW = 72, SMAT = 128 * SROW;

    const int tid = threadIdx.x, wid = tid >> 5, lane = tid & 31;
    const int wm = wid >> 1, wn = wid & 1;
    const int g = lane >> 2, ti = lane & 3;
    const int m0 = blockIdx.y * 128, n0 = blockIdx.x * 128;

    float acc[2][8][4];
    #pragma unroll
    for (int a = 0; a < 2; a++)
        #pragma unroll
        for (int b = 0; b < 8; b++)
            #pragma unroll
            for (int c = 0; c < 4; c++) acc[a][b][c] = 0.f;

    auto load_stage = [&](int s) {
        int pass = (s >= KT);
        int kofs = (pass ? s - KT : s) * 64;
        const __nv_bfloat16* Wg = pass ? Wlo : Whi;
        __nv_bfloat16* as = smbuf + (s & 1) * SMAT;
        __nv_bfloat16* bs = smbuf + 2 * SMAT + (s & 1) * SMAT;
        #pragma unroll
        for (int it = 0; it < 4; it++) {
            int cid = tid + it * 256;
            int r = cid >> 3, c = (cid & 7) * 8;
            cp_async16(&as[r * SROW + c], A  + (size_t)(m0 + r) * K + kofs + c);
            cp_async16(&bs[r * SROW + c], Wg + (size_t)(n0 + r) * K + kofs + c);
        }
        asm volatile("cp.async.commit_group;\n");
    };

    load_stage(0);
    const int NKT = 2 * KT;
    for (int s = 0; s < NKT; s++) {
        asm volatile("cp.async.wait_group 0;\n");
        __syncthreads();
        if (s + 1 < NKT) load_stage(s + 1);
        const __nv_bfloat16* as = smbuf + (s & 1) * SMAT;
        const __nv_bfloat16* bs = smbuf + 2 * SMAT + (s & 1) * SMAT;
        #pragma unroll
        for (int kk = 0; kk < 4; kk++) {
            int kc = kk * 16 + 2 * ti;
            unsigned af[2][4], bq[8][2];
            #pragma unroll
            for (int mt = 0; mt < 2; mt++) {
                int r = wm * 32 + mt * 16 + g;
                af[mt][0] = *(const unsigned*)(as + r * SROW + kc);
                af[mt][1] = *(const unsigned*)(as + (r + 8) * SROW + kc);
                af[mt][2] = *(const unsigned*)(as + r * SROW + kc + 8);
                af[mt][3] = *(const unsigned*)(as + (r + 8) * SROW + kc + 8);
            }
            #pragma unroll
            for (int nt = 0; nt < 8; nt++) {
                int r = wn * 64 + nt * 8 + g;
                bq[nt][0] = *(const unsigned*)(bs + r * SROW + kc);
                bq[nt][1] = *(const unsigned*)(bs + r * SROW + kc + 8);
            }
            #pragma unroll
            for (int mt = 0; mt < 2; mt++)
                #pragma unroll
                for (int nt = 0; nt < 8; nt++)
                    asm volatile(
                        "mma.sync.aligned.m16n8k16.row.col.f32.bf16.bf16.f32 "
                        "{%0,%1,%2,%3},{%4,%5,%6,%7},{%8,%9},{%0,%1,%2,%3};"
                        : "+f"(acc[mt][nt][0]), "+f"(acc[mt][nt][1]),
                          "+f"(acc[mt][nt][2]), "+f"(acc[mt][nt][3])
                        : "r"(af[mt][0]), "r"(af[mt][1]), "r"(af[mt][2]), "r"(af[mt][3]),
                          "r"(bq[nt][0]), "r"(bq[nt][1]));
        }
    }

    // fused epilogue
    if (EPI == 1) {
        float mn1 = __int_as_float(g_mn1), mx1 = __int_as_float(g_mx1);
        float sc = (mx1 - mn1) * (1.0f / 255.0f);
        float lmn = __int_as_float(0x7f800000), lmx = -lmn;
        #pragma unroll
        for (int mt = 0; mt < 2; mt++)
            #pragma unroll
            for (int nt = 0; nt < 8; nt++)
                #pragma unroll
                for (int c = 0; c < 4; c++) {
                    int row = m0 + wm * 32 + mt * 16 + g + ((c & 2) << 2);
                    int col = n0 + wn * 64 + nt * 8 + 2 * ti + (c & 1);
                    float hv = acc[mt][nt][c] * sc + mn1 * S[col];
                    hv = fmaxf(hv, 0.f);
                    out[(size_t)row * N + col] = hv;
                    lmn = fminf(lmn, hv); lmx = fmaxf(lmx, hv);
                }
        #pragma unroll
        for (int o = 16; o; o >>= 1) {
            lmn = fminf(lmn, __shfl_xor_sync(0xffffffffu, lmn, o));
            lmx = fmaxf(lmx, __shfl_xor_sync(0xffffffffu, lmx, o));
        }
        if (lane == 0) { atomicMinF(&g_mn2, lmn); atomicMaxF(&g_mx2, lmx); }
    } else {
        float mn2 = __int_as_float(g_mn2), mx2 = __int_as_float(g_mx2);
        float sc = (mx2 - mn2) * (1.0f / 255.0f);
        #pragma unroll
        for (int mt = 0; mt < 2; mt++)
            #pragma unroll
            for (int nt = 0; nt < 8; nt++)
                #pragma unroll
                for (int c = 0; c < 4; c++) {
                    int row = m0 + wm * 32 + mt * 16 + g + ((c & 2) << 2);
                    int col = n0 + wn * 64 + nt * 8 + 2 * ti + (c & 1);
                    out[(size_t)row * N + col] = acc[mt][nt][c] * sc + mn2 * S[col];
                }
    }
}

// sigmoid(gate)*tanh(extract)*mask, summed over 12 neighbors
__global__ void k_gate(const float* __restrict__ mask) {
    int idx = blockIdx.x * 256 + threadIdx.x;       // < BA_ROWS*FN
    int ba = idx >> 6, j = idx & 63;
    float acc = 0.f;
    #pragma unroll
    for (int nb = 0; nb < NBRN; nb++) {
        int m = ba * NBRN + nb;
        float gv = g_c2[m * H2 + j];
        float ev = g_c2[m * H2 + 64 + j];
        acc += (1.f / (1.f + expf(-gv))) * tanhf(ev) * mask[m];
    }
    g_ns[idx] = acc;
}

// deterministic per-feature BN statistics (one block per feature, two-pass)
__global__ void k_stats() {
    int j = blockIdx.x, t = threadIdx.x;
    __shared__ float red[256];
    __shared__ float mean_s;
    float s = 0.f;
    for (int r = t; r < BA_ROWS; r += 256) s += g_ns[r * FN + j];
    red[t] = s; __syncthreads();
    #pragma unroll
    for (int k = 128; k; k >>= 1) { if (t < k) red[t] += red[t + k]; __syncthreads(); }
    if (t == 0) mean_s = red[0] / (float)BA_ROWS;
    __syncthreads();
    float mean = mean_s, s2 = 0.f;
    for (int r = t; r < BA_ROWS; r += 256) { float d = g_ns[r * FN + j] - mean; s2 += d * d; }
    red[t] = s2; __syncthreads();
    #pragma unroll
    for (int k = 128; k; k >>= 1) { if (t < k) red[t] += red[t + k]; __syncthreads(); }
    if (t == 0) { g_mean[j] = mean; g_var[j] = red[0] / (float)BA_ROWS; }
}

__global__ void k_final(const float* __restrict__ node, const float* __restrict__ gamma,
                        const float* __restrict__ beta, float* __restrict__ out) {
    int idx = blockIdx.x * 256 + threadIdx.x;       // < BA_ROWS*FN
    int j = idx & 63;
    float bn = (g_ns[idx] - g_mean[j]) / sqrtf(g_var[j] + 1e-5f) * gamma[j] + beta[j];
    out[idx] = fmaxf(node[idx] + bn, 0.f);
}

// ---------------- launcher ----------------
extern "C" void kernel_launch(void* const* d_in, const int* in_sizes, int n_in,
                              void* d_out, int out_size) {
    const float* node  = (const float*)d_in[0];
    const float* edge  = (const float*)d_in[1];
    const float* maskp = (const float*)d_in[2];
    const float* cond1 = (const float*)d_in[3];
    const float* cond2 = (const float*)d_in[4];
    const float* eps1  = (const float*)d_in[5];
    const float* eps2  = (const float*)d_in[6];
    const float* gamma = (const float*)d_in[7];
    const float* beta  = (const float*)d_in[8];
    float* out = (float*)d_out;

    const int SMEM = 4 * 128 * 72 * (int)sizeof(__nv_bfloat16);   // 73728 B
    cudaFuncSetAttribute(k_gemm<1>, cudaFuncAttributeMaxDynamicSharedMemorySize, SMEM);
    cudaFuncSetAttribute(k_gemm<2>, cudaFuncAttributeMaxDynamicSharedMemorySize, SMEM);

    k_init<<<1, 1>>>();
    k_c1<<<(M_ROWS * F1) / 256, 256>>>(node, edge);
    k_prep1<<<H1, 128>>>(cond1, eps1);
    k_prep2<<<H2, 256>>>(cond2, eps2);
    k_bits1<<<(M_ROWS * K1) / 256, 256>>>();
    k_gemm<1><<<dim3(H1 / 128, M_ROWS / 128), 256, SMEM>>>();
    k_bits2<<<(int)(((size_t)M_ROWS * K2) / 256), 256>>>();
    k_gemm<2><<<dim3(1, M_ROWS / 128), 256, SMEM>>>();
    k_gate<<<(BA_ROWS * FN) / 256, 256>>>(maskp);
    k_stats<<<FN, 256>>>();
    k_final<<<(BA_ROWS * FN) / 256, 256>>>(node, gamma, beta, out);
}

// round 3
// speedup vs baseline: 1.5850x; 1.5850x over previous
#include <cuda_runtime.h>
#include <cuda_bf16.h>
#include <math.h>

// ---------------- problem constants ----------------
#define BB    16
#define AT    96
#define NBRN  12
#define M_ROWS 18432      /* BB*AT*NBRN */
#define BA_ROWS 1536      /* BB*AT */
#define F1    128         /* Fn+Fe */
#define H1    512
#define H2    128
#define FN    64
#define K1    1024        /* F1 * 8 planes, k = i*8+b */
#define K2    4096        /* H1 * 8 planes */

// ---------------- scratch ----------------
__device__ __nv_bfloat16  g_W1hi[H1 * K1];
__device__ __nv_bfloat16  g_W1lo[H1 * K1];
__device__ __nv_bfloat16  g_W2hi[H2 * K2];
__device__ __nv_bfloat16  g_W2lo[H2 * K2];
__device__ float          g_S1[H1];
__device__ float          g_S2[H2];
__device__ float          g_h[(size_t)M_ROWS * H1];             // 37.7 MB
__device__ float          g_c2[M_ROWS * H2];                    // 9.4 MB
__device__ float          g_ns[BA_ROWS * FN];
__device__ float          g_mean[FN], g_var[FN];
__device__ int            g_mn1, g_mx1, g_mn2, g_mx2;           // float bits

// ---------------- helpers ----------------
__device__ __forceinline__ void atomicMinF(int* a, float v) {
    if (v >= 0.f) atomicMin(a, __float_as_int(v));
    else          atomicMax((unsigned int*)a, (unsigned int)__float_as_int(v));
}
__device__ __forceinline__ void atomicMaxF(int* a, float v) {
    if (v >= 0.f) atomicMax(a, __float_as_int(v));
    else          atomicMin((unsigned int*)a, (unsigned int)__float_as_int(v));
}
__device__ __forceinline__ void cp_async16(void* s, const void* g) {
    unsigned sa = (unsigned)__cvta_generic_to_shared(s);
    asm volatile("cp.async.cg.shared.global [%0], [%1], 16;\n" :: "r"(sa), "l"(g));
}
__device__ __forceinline__ void ldmx4(unsigned& r0, unsigned& r1, unsigned& r2, unsigned& r3,
                                      const __nv_bfloat16* p) {
    unsigned a = (unsigned)__cvta_generic_to_shared(p);
    asm volatile("ldmatrix.sync.aligned.m8n8.x4.shared.b16 {%0,%1,%2,%3},[%4];"
                 : "=r"(r0), "=r"(r1), "=r"(r2), "=r"(r3) : "r"(a));
}
// pack bits (b, b+1) of q-byte as two bf16 {0,1} in one u32 (lo = bit b)
__device__ __forceinline__ unsigned pack2(unsigned by, int b) {
    unsigned u = by >> b;
    return (u & 1u) * 0x3F80u | ((u >> 1) & 1u) * 0x3F800000u;
}
__device__ __forceinline__ unsigned qz(float x, float mn, float mx) {
    float t = (x - mn) / (mx - mn) * 255.0f;
    int q = (int)t; q = q < 0 ? 0 : (q > 255 ? 255 : q);
    return (unsigned)q;
}

// ---------------- small kernels ----------------
__global__ void k_init() {
    g_mn1 = 0x7f800000; g_mx1 = (int)0xff800000;
    g_mn2 = 0x7f800000; g_mx2 = (int)0xff800000;
}

// global min/max over node ∪ edge (== min/max of concat c1)
#define NODE_N (BA_ROWS * FN)
#define EDGE_N (M_ROWS * 64)
__global__ void k_minmax(const float* __restrict__ node, const float* __restrict__ edge) {
    int idx = blockIdx.x * 256 + threadIdx.x;
    float v = (idx < NODE_N) ? node[idx] : edge[idx - NODE_N];
    float mn = v, mx = v;
    #pragma unroll
    for (int o = 16; o; o >>= 1) {
        mn = fminf(mn, __shfl_xor_sync(0xffffffffu, mn, o));
        mx = fmaxf(mx, __shfl_xor_sync(0xffffffffu, mx, o));
    }
    __shared__ float smn[8], smx[8];
    int lane = threadIdx.x & 31, w = threadIdx.x >> 5;
    if (lane == 0) { smn[w] = mn; smx[w] = mx; }
    __syncthreads();
    if (threadIdx.x == 0) {
        float bmn = smn[0], bmx = smx[0];
        #pragma unroll
        for (int i = 1; i < 8; i++) { bmn = fminf(bmn, smn[i]); bmx = fmaxf(bmx, smx[i]); }
        atomicMinF(&g_mn1, bmn); atomicMaxF(&g_mx1, bmx);
    }
}

// layer-1 weights: Weff[o][k=i*8+b] = 2^b*(w+eps*|w|*0.1), bf16 hi/lo split.
__global__ void k_prep1(const float* __restrict__ cond1, const float* __restrict__ eps1) {
    int o = blockIdx.x, i = threadIdx.x;            // 512 x 128
    float w = cond1[o * F1 + i];
    float aw = fabsf(w) * 0.1f;
    float s7 = 0.f;
    #pragma unroll
    for (int b = 0; b < 8; b++) {
        float wn = w + eps1[b * (H1 * F1) + o * F1 + i] * aw;
        if (b == 7) s7 = wn;
        float v = wn * (float)(1 << b);
        __nv_bfloat16 hi = __float2bfloat16(v);
        float lo = v - __bfloat162float(hi);
        g_W1hi[o * K1 + i * 8 + b] = hi;
        g_W1lo[o * K1 + i * 8 + b] = __float2bfloat16(lo);
    }
    __shared__ float red[128];
    red[i] = s7; __syncthreads();
    #pragma unroll
    for (int s = 64; s; s >>= 1) { if (i < s) red[i] += red[i + s]; __syncthreads(); }
    if (i == 0) g_S1[o] = red[0];
}

__global__ void k_prep2(const float* __restrict__ cond2, const float* __restrict__ eps2) {
    int o = blockIdx.x, t = threadIdx.x;            // 128 x 256
    float sr = 0.f;
    for (int i = t; i < H1; i += 256) {
        float w = cond2[o * H1 + i];
        float aw = fabsf(w) * 0.1f;
        sr += cond2[H2 * H1 + o * H1 + i];
        #pragma unroll
        for (int b = 0; b < 8; b++) {
            float wn = w + eps2[b * (H2 * H1) + o * H1 + i] * aw;
            float v = wn * (float)(1 << b);
            __nv_bfloat16 hi = __float2bfloat16(v);
            float lo = v - __bfloat162float(hi);
            g_W2hi[o * K2 + i * 8 + b] = hi;
            g_W2lo[o * K2 + i * 8 + b] = __float2bfloat16(lo);
        }
    }
    __shared__ float red[256];
    red[t] = sr; __syncthreads();
    #pragma unroll
    for (int s = 128; s; s >>= 1) { if (t < s) red[t] += red[t + s]; __syncthreads(); }
    if (t == 0) g_S2[o] = red[0];
}

// ---------------- fused bit-plane GEMM ----------------
// C[M,N] = bits(q(src)) @ (Whi + Wlo)^T, A fragments built in registers from a
// per-CTA smem q byte array. CTA tile 128x128, BK=64, 8 warps, warp tile 32x64.
// B double-pumped (hi & lo tiles per stage), 3-stage cp.async ring pipeline.
template<int EPI>
__global__ void __launch_bounds__(256, 1) k_gemm(const float* __restrict__ node,
                                                 const float* __restrict__ edge) {
    constexpr int SC = (EPI == 1) ? F1 : H1;      // source cols
    constexpr int K  = SC * 8;
    constexpr int N  = (EPI == 1) ? H1 : H2;
    constexpr int KT = K / 64;
    constexpr int QROWB = SC + 16;                // q row stride (8B-aligned)
    const __nv_bfloat16* Whi = (EPI == 1) ? g_W1hi : g_W2hi;
    const __nv_bfloat16* Wlo = (EPI == 1) ? g_W1lo : g_W2lo;
    const float*         S   = (EPI == 1) ? g_S1 : g_S2;
    float*               out = (EPI == 1) ? g_h : g_c2;

    extern __shared__ char smraw[];
    unsigned char* qs = (unsigned char*)smraw;                       // 128*QROWB
    __nv_bfloat16* bsm = (__nv_bfloat16*)(smraw + 128 * QROWB);      // 6 x 128*72

    const int tid = threadIdx.x, wid = tid >> 5, lane = tid & 31;
    const int wm = wid >> 1, wn = wid & 1;
    const int g = lane >> 2, ti = lane & 3, ti2 = 2 * ti;
    const int m0 = blockIdx.y * 128, n0 = blockIdx.x * 128;

    float mn, mx;
    if (EPI == 1) { mn = __int_as_float(g_mn1); mx = __int_as_float(g_mx1); }
    else          { mn = __int_as_float(g_mn2); mx = __int_as_float(g_mx2); }

    // ---- phase 1: quantize source slab into smem q bytes ----
    constexpr int WPR = SC / 4;
    #pragma unroll 1
    for (int it = 0; it < (128 * WPR) / 256; it++) {
        int idx = tid + it * 256;
        int r = idx / WPR, wc = idx % WPR;
        float4 v;
        if (EPI == 1) {
            int m = m0 + r, j = wc * 4;
            if (j < FN) v = *(const float4*)(node + (m / NBRN) * FN + j);
            else        v = *(const float4*)(edge + (size_t)m * 64 + (j - 64));
        } else {
            v = *(const float4*)(g_h + (size_t)(m0 + r) * H1 + wc * 4);
        }
        unsigned p = qz(v.x, mn, mx) | (qz(v.y, mn, mx) << 8) |
                     (qz(v.z, mn, mx) << 16) | (qz(v.w, mn, mx) << 24);
        *(unsigned*)(qs + r * QROWB + wc * 4) = p;
    }

    // ---- phase 2: k-loop ----
    float acc[2][8][4];
    #pragma unroll
    for (int a = 0; a < 2; a++)
        #pragma unroll
        for (int b = 0; b < 8; b++)
            #pragma unroll
            for (int c = 0; c < 4; c++) acc[a][b][c] = 0.f;

    auto loadB = [&](int s) {
        int kofs = s * 64, buf = s % 3;
        __nv_bfloat16* bh = bsm + (buf * 2 + 0) * (128 * 72);
        __nv_bfloat16* bl = bsm + (buf * 2 + 1) * (128 * 72);
        #pragma unroll
        for (int it2 = 0; it2 < 4; it2++) {
            int cid = tid + it2 * 256;
            int r = cid >> 3, c = (cid & 7) * 8;
            cp_async16(&bh[r * 72 + c], Whi + (size_t)(n0 + r) * K + kofs + c);
            cp_async16(&bl[r * 72 + c], Wlo + (size_t)(n0 + r) * K + kofs + c);
        }
        asm volatile("cp.async.commit_group;\n");
    };

    // ldmatrix per-lane base: matrices grouped (nt-pair p, half): lm=lane>>3
    const int lm = lane >> 3, lr = lane & 7;
    const int lmbase = (wn * 64 + (lm >> 1) * 8 + lr) * 72 + (lm & 1) * 8;

    loadB(0);
    loadB(1);
    __syncthreads();   // also covers phase-1 q writes
    #pragma unroll 1
    for (int s = 0; s < KT; s++) {
        // groups s and (maybe) s+1 are pending; ensure group s has landed.
        if (s + 1 < KT) asm volatile("cp.async.wait_group 1;\n");
        else            asm volatile("cp.async.wait_group 0;\n");
        __syncthreads();   // all warps done reading buffer (s-1)%3 -> (s+2)%3 free
        if (s + 2 < KT) loadB(s + 2);

        uint2 qv[2][2];
        #pragma unroll
        for (int mt = 0; mt < 2; mt++)
            #pragma unroll
            for (int h = 0; h < 2; h++) {
                int r = wm * 32 + mt * 16 + h * 8 + g;
                qv[mt][h] = *(const uint2*)(qs + r * QROWB + s * 8);
            }
        const __nv_bfloat16* bh = bsm + ((s % 3) * 2 + 0) * (128 * 72);
        const __nv_bfloat16* bl = bsm + ((s % 3) * 2 + 1) * (128 * 72);

        #pragma unroll
        for (int kk = 0; kk < 4; kk++) {
            unsigned af[2][4];
            #pragma unroll
            for (int mt = 0; mt < 2; mt++) {
                unsigned w0 = (kk < 2) ? qv[mt][0].x : qv[mt][0].y;
                unsigned w1 = (kk < 2) ? qv[mt][1].x : qv[mt][1].y;
                unsigned b00 = (w0 >> (((2 * kk) & 3) * 8)) & 0xFFu;
                unsigned b01 = (w0 >> (((2 * kk + 1) & 3) * 8)) & 0xFFu;
                unsigned b10 = (w1 >> (((2 * kk) & 3) * 8)) & 0xFFu;
                unsigned b11 = (w1 >> (((2 * kk + 1) & 3) * 8)) & 0xFFu;
                af[mt][0] = pack2(b00, ti2);
                af[mt][1] = pack2(b10, ti2);
                af[mt][2] = pack2(b01, ti2);
                af[mt][3] = pack2(b11, ti2);
            }
            unsigned bqh[8][2], bql[8][2];
            #pragma unroll
            for (int p = 0; p < 4; p++) {
                ldmx4(bqh[2 * p][0], bqh[2 * p][1], bqh[2 * p + 1][0], bqh[2 * p + 1][1],
                      bh + lmbase + p * (16 * 72) + kk * 16);
                ldmx4(bql[2 * p][0], bql[2 * p][1], bql[2 * p + 1][0], bql[2 * p + 1][1],
                      bl + lmbase + p * (16 * 72) + kk * 16);
            }
            #pragma unroll
            for (int mt = 0; mt < 2; mt++)
                #pragma unroll
                for (int nt = 0; nt < 8; nt++) {
                    asm volatile(
                        "mma.sync.aligned.m16n8k16.row.col.f32.bf16.bf16.f32 "
                        "{%0,%1,%2,%3},{%4,%5,%6,%7},{%8,%9},{%0,%1,%2,%3};"
                        : "+f"(acc[mt][nt][0]), "+f"(acc[mt][nt][1]),
                          "+f"(acc[mt][nt][2]), "+f"(acc[mt][nt][3])
                        : "r"(af[mt][0]), "r"(af[mt][1]), "r"(af[mt][2]), "r"(af[mt][3]),
                          "r"(bqh[nt][0]), "r"(bqh[nt][1]));
                    asm volatile(
                        "mma.sync.aligned.m16n8k16.row.col.f32.bf16.bf16.f32 "
                        "{%0,%1,%2,%3},{%4,%5,%6,%7},{%8,%9},{%0,%1,%2,%3};"
                        : "+f"(acc[mt][nt][0]), "+f"(acc[mt][nt][1]),
                          "+f"(acc[mt][nt][2]), "+f"(acc[mt][nt][3])
                        : "r"(af[mt][0]), "r"(af[mt][1]), "r"(af[mt][2]), "r"(af[mt][3]),
                          "r"(bql[nt][0]), "r"(bql[nt][1]));
                }
        }
    }

    // ---- epilogue ----
    if (EPI == 1) {
        float sc = (mx - mn) * (1.0f / 255.0f);
        float lmn = __int_as_float(0x7f800000), lmx = -lmn;
        #pragma unroll
        for (int mt = 0; mt < 2; mt++)
            #pragma unroll
            for (int nt = 0; nt < 8; nt++)
                #pragma unroll
                for (int c = 0; c < 4; c++) {
                    int row = m0 + wm * 32 + mt * 16 + g + ((c & 2) << 2);
                    int col = n0 + wn * 64 + nt * 8 + ti2 + (c & 1);
                    float hv = acc[mt][nt][c] * sc + mn * S[col];
                    hv = fmaxf(hv, 0.f);
                    out[(size_t)row * N + col] = hv;
                    lmn = fminf(lmn, hv); lmx = fmaxf(lmx, hv);
                }
        #pragma unroll
        for (int o = 16; o; o >>= 1) {
            lmn = fminf(lmn, __shfl_xor_sync(0xffffffffu, lmn, o));
            lmx = fmaxf(lmx, __shfl_xor_sync(0xffffffffu, lmx, o));
        }
        if (lane == 0) { atomicMinF(&g_mn2, lmn); atomicMaxF(&g_mx2, lmx); }
    } else {
        float sc = (mx - mn) * (1.0f / 255.0f);
        #pragma unroll
        for (int mt = 0; mt < 2; mt++)
            #pragma unroll
            for (int nt = 0; nt < 8; nt++)
                #pragma unroll
                for (int c = 0; c < 4; c++) {
                    int row = m0 + wm * 32 + mt * 16 + g + ((c & 2) << 2);
                    int col = n0 + wn * 64 + nt * 8 + ti2 + (c & 1);
                    out[(size_t)row * N + col] = acc[mt][nt][c] * sc + mn * S[col];
                }
    }
}

// sigmoid(gate)*tanh(extract)*mask, summed over 12 neighbors
__global__ void k_gate(const float* __restrict__ mask) {
    int idx = blockIdx.x * 256 + threadIdx.x;       // < BA_ROWS*FN
    int ba = idx >> 6, j = idx & 63;
    float acc = 0.f;
    #pragma unroll
    for (int nb = 0; nb < NBRN; nb++) {
        int m = ba * NBRN + nb;
        float gv = g_c2[m * H2 + j];
        float ev = g_c2[m * H2 + 64 + j];
        acc += (1.f / (1.f + expf(-gv))) * tanhf(ev) * mask[m];
    }
    g_ns[idx] = acc;
}

// deterministic per-feature BN statistics
__global__ void k_stats() {
    int j = blockIdx.x, t = threadIdx.x;
    __shared__ float red[256];
    __shared__ float mean_s;
    float s = 0.f;
    for (int r = t; r < BA_ROWS; r += 256) s += g_ns[r * FN + j];
    red[t] = s; __syncthreads();
    #pragma unroll
    for (int k = 128; k; k >>= 1) { if (t < k) red[t] += red[t + k]; __syncthreads(); }
    if (t == 0) mean_s = red[0] / (float)BA_ROWS;
    __syncthreads();
    float mean = mean_s, s2 = 0.f;
    for (int r = t; r < BA_ROWS; r += 256) { float d = g_ns[r * FN + j] - mean; s2 += d * d; }
    red[t] = s2; __syncthreads();
    #pragma unroll
    for (int k = 128; k; k >>= 1) { if (t < k) red[t] += red[t + k]; __syncthreads(); }
    if (t == 0) { g_mean[j] = mean; g_var[j] = red[0] / (float)BA_ROWS; }
}

__global__ void k_final(const float* __restrict__ node, const float* __restrict__ gamma,
                        const float* __restrict__ beta, float* __restrict__ out) {
    int idx = blockIdx.x * 256 + threadIdx.x;       // < BA_ROWS*FN
    int j = idx & 63;
    float bn = (g_ns[idx] - g_mean[j]) / sqrtf(g_var[j] + 1e-5f) * gamma[j] + beta[j];
    out[idx] = fmaxf(node[idx] + bn, 0.f);
}

// ---------------- launcher ----------------
extern "C" void kernel_launch(void* const* d_in, const int* in_sizes, int n_in,
                              void* d_out, int out_size) {
    const float* node  = (const float*)d_in[0];
    const float* edge  = (const float*)d_in[1];
    const float* maskp = (const float*)d_in[2];
    const float* cond1 = (const float*)d_in[3];
    const float* cond2 = (const float*)d_in[4];
    const float* eps1  = (const float*)d_in[5];
    const float* eps2  = (const float*)d_in[6];
    const float* gamma = (const float*)d_in[7];
    const float* beta  = (const float*)d_in[8];
    float* out = (float*)d_out;

    const int SMEM1 = 128 * (F1 + 16) + 6 * 128 * 72 * (int)sizeof(__nv_bfloat16);  // 129024
    const int SMEM2 = 128 * (H1 + 16) + 6 * 128 * 72 * (int)sizeof(__nv_bfloat16);  // 178176
    cudaFuncSetAttribute(k_gemm<1>, cudaFuncAttributeMaxDynamicSharedMemorySize, SMEM1);
    cudaFuncSetAttribute(k_gemm<2>, cudaFuncAttributeMaxDynamicSharedMemorySize, SMEM2);

    k_init<<<1, 1>>>();
    k_minmax<<<(NODE_N + EDGE_N) / 256, 256>>>(node, edge);
    k_prep1<<<H1, 128>>>(cond1, eps1);
    k_prep2<<<H2, 256>>>(cond2, eps2);
    k_gemm<1><<<dim3(H1 / 128, M_ROWS / 128), 256, SMEM1>>>(node, edge);
    k_gemm<2><<<dim3(1, M_ROWS / 128), 256, SMEM2>>>(nullptr, nullptr);
    k_gate<<<(BA_ROWS * FN) / 256, 256>>>(maskp);
    k_stats<<<FN, 256>>>();
    k_final<<<(BA_ROWS * FN) / 256, 256>>>(node, gamma, beta, out);
}

// round 6
// speedup vs baseline: 1.8060x; 1.1394x over previous
#include <cuda_runtime.h>
#include <cuda_fp16.h>
#include <math.h>

// ---------------- problem constants ----------------
#define BB    16
#define AT    96
#define NBRN  12
#define M_ROWS 18432      /* BB*AT*NBRN */
#define BA_ROWS 1536      /* BB*AT */
#define F1    128         /* Fn+Fe */
#define H1    512
#define H2    128
#define FN    64
#define K1    1024        /* 8 planes * F1, plane-major k = b*SC + i */
#define K2    4096        /* 8 planes * H1 */
#define K1L   512         /* 4 lo planes * F1 */
#define K2L   2048        /* 4 lo planes * H1 */

// ---------------- scratch ----------------
__device__ __half  g_W1hi[H1 * K1];
__device__ __half  g_W1lo[H1 * K1L];
__device__ __half  g_W2hi[H2 * K2];
__device__ __half  g_W2lo[H2 * K2L];
__device__ float   g_S1[H1];
__device__ float   g_S2[H2];
__device__ float   g_h[(size_t)M_ROWS * H1];
__device__ float   g_c2[M_ROWS * H2];
__device__ float   g_ns[BA_ROWS * FN];
__device__ float   g_mean[FN], g_var[FN];
__device__ int     g_mn1, g_mx1, g_mn2, g_mx2;   // float bits

// ---------------- helpers ----------------
__device__ __forceinline__ void atomicMinF(int* a, float v) {
    if (v >= 0.f) atomicMin(a, __float_as_int(v));
    else          atomicMax((unsigned int*)a, (unsigned int)__float_as_int(v));
}
__device__ __forceinline__ void atomicMaxF(int* a, float v) {
    if (v >= 0.f) atomicMax(a, __float_as_int(v));
    else          atomicMin((unsigned int*)a, (unsigned int)__float_as_int(v));
}
__device__ __forceinline__ void cp_async16(void* s, const void* g) {
    unsigned sa = (unsigned)__cvta_generic_to_shared(s);
    asm volatile("cp.async.cg.shared.global [%0], [%1], 16;\n" :: "r"(sa), "l"(g));
}
__device__ __forceinline__ void ldmx4(unsigned& r0, unsigned& r1, unsigned& r2, unsigned& r3,
                                      const __half* p) {
    unsigned a = (unsigned)__cvta_generic_to_shared(p);
    asm volatile("ldmatrix.sync.aligned.m8n8.x4.shared.b16 {%0,%1,%2,%3},[%4];"
                 : "=r"(r0), "=r"(r1), "=r"(r2), "=r"(r3) : "r"(a));
}
__device__ __forceinline__ unsigned qz(float x, float mn, float mx) {
    float t = (x - mn) / (mx - mn) * 255.0f;
    int q = (int)t; q = q < 0 ? 0 : (q > 255 ? 255 : q);
    return (unsigned)q;
}
// gather bit b of 8 packed bytes -> 8 bits (carry-free multiply transpose)
__device__ __forceinline__ unsigned bits8(unsigned long long x, int b) {
    return (unsigned)(((( x >> b) & 0x0101010101010101ULL) * 0x0102040810204080ULL) >> 56);
}

// ---------------- small kernels ----------------
__global__ void k_init() {
    g_mn1 = 0x7f800000; g_mx1 = (int)0xff800000;
    g_mn2 = 0x7f800000; g_mx2 = (int)0xff800000;
}

#define NODE_N (BA_ROWS * FN)
#define EDGE_N (M_ROWS * 64)
__global__ void k_minmax(const float* __restrict__ node, const float* __restrict__ edge) {
    int idx = blockIdx.x * 256 + threadIdx.x;
    float v = (idx < NODE_N) ? node[idx] : edge[idx - NODE_N];
    float mn = v, mx = v;
    #pragma unroll
    for (int o = 16; o; o >>= 1) {
        mn = fminf(mn, __shfl_xor_sync(0xffffffffu, mn, o));
        mx = fmaxf(mx, __shfl_xor_sync(0xffffffffu, mx, o));
    }
    __shared__ float smn[8], smx[8];
    int lane = threadIdx.x & 31, w = threadIdx.x >> 5;
    if (lane == 0) { smn[w] = mn; smx[w] = mx; }
    __syncthreads();
    if (threadIdx.x == 0) {
        float bmn = smn[0], bmx = smx[0];
        #pragma unroll
        for (int i = 1; i < 8; i++) { bmn = fminf(bmn, smn[i]); bmx = fmaxf(bmx, smx[i]); }
        atomicMinF(&g_mn1, bmn); atomicMaxF(&g_mx1, bmx);
    }
}

// layer-1 weights, plane-major: Whi[o][b*F1+i] = fp16(2^b*(w+eps*|w|*0.1));
// lo residual for planes 4..7.
__global__ void k_prep1(const float* __restrict__ cond1, const float* __restrict__ eps1) {
    int o = blockIdx.x, i = threadIdx.x;            // 512 x 128
    float w = cond1[o * F1 + i];
    float aw = fabsf(w) * 0.1f;
    float s7 = 0.f;
    #pragma unroll
    for (int b = 0; b < 8; b++) {
        float wn = w + eps1[b * (H1 * F1) + o * F1 + i] * aw;
        if (b == 7) s7 = wn;
        float v = wn * (float)(1 << b);
        __half hi = __float2half_rn(v);
        g_W1hi[o * K1 + b * F1 + i] = hi;
        if (b >= 4)
            g_W1lo[o * K1L + (b - 4) * F1 + i] = __float2half_rn(v - __half2float(hi));
    }
    __shared__ float red[128];
    red[i] = s7; __syncthreads();
    #pragma unroll
    for (int s = 64; s; s >>= 1) { if (i < s) red[i] += red[i + s]; __syncthreads(); }
    if (i == 0) g_S1[o] = red[0];
}

__global__ void k_prep2(const float* __restrict__ cond2, const float* __restrict__ eps2) {
    int o = blockIdx.x, t = threadIdx.x;            // 128 x 256
    float sr = 0.f;
    for (int i = t; i < H1; i += 256) {
        float w = cond2[o * H1 + i];
        float aw = fabsf(w) * 0.1f;
        sr += cond2[H2 * H1 + o * H1 + i];
        #pragma unroll
        for (int b = 0; b < 8; b++) {
            float wn = w + eps2[b * (H2 * H1) + o * H1 + i] * aw;
            float v = wn * (float)(1 << b);
            __half hi = __float2half_rn(v);
            g_W2hi[o * K2 + b * H1 + i] = hi;
            if (b >= 4)
                g_W2lo[o * K2L + (b - 4) * H1 + i] = __float2half_rn(v - __half2float(hi));
        }
    }
    __shared__ float red[256];
    red[t] = sr; __syncthreads();
    #pragma unroll
    for (int s = 128; s; s >>= 1) { if (t < s) red[t] += red[t + s]; __syncthreads(); }
    if (t == 0) g_S2[o] = red[0];
}

// ---------------- fused bit-plane GEMM (mma.sync fp16, plane-major) ----------------
// Stages: KTH hi stages (planes 0..7) + KTL lo stages (planes 4..7 residual).
// A fragments from smem bit-plane bitmaps; B via 3-deep cp.async ring.
template<int EPI>
__global__ void __launch_bounds__(256) k_tc(const float* __restrict__ node,
                                            const float* __restrict__ edge) {
    constexpr int SC  = (EPI == 1) ? F1 : H1;     // source cols
    constexpr int N   = (EPI == 1) ? H1 : H2;
    constexpr int SPP = SC / 64;                  // stages per plane
    constexpr int KTH = 8 * SPP;
    constexpr int KTL = 4 * SPP;
    constexpr int NST = KTH + KTL;
    constexpr int KHI = 8 * SC, KLO = 4 * SC;     // W row strides
    constexpr int QROWB = SC + 16;
    constexpr int BPR   = SC / 8 + 8;             // bitmap row stride (bytes)
    constexpr int SROW  = 72;                     // B tile row stride (halves)
    constexpr int BTILE = 128 * SROW;             // halves per tile
    const __half* Whi = (EPI == 1) ? g_W1hi : g_W2hi;
    const __half* Wlo = (EPI == 1) ? g_W1lo : g_W2lo;
    const float*  S   = (EPI == 1) ? g_S1 : g_S2;
    float*        out = (EPI == 1) ? g_h : g_c2;

    extern __shared__ char smraw[];
    __half*        bsm = (__half*)smraw;                              // 3 B tiles
    unsigned char* bp  = (unsigned char*)(smraw + 3 * BTILE * 2);     // bitmaps
    unsigned char* qs  = bp + 8 * 128 * BPR;                          // q slab

    const int tid = threadIdx.x, wid = tid >> 5, lane = tid & 31;
    const int wm = wid >> 1, wn = wid & 1;
    const int g = lane >> 2, ti2 = (lane & 3) * 2;
    const int m0 = blockIdx.y * 128, n0 = blockIdx.x * 128;

    float mn, mx;
    if (EPI == 1) { mn = __int_as_float(g_mn1); mx = __int_as_float(g_mx1); }
    else          { mn = __int_as_float(g_mn2); mx = __int_as_float(g_mx2); }

    // ---- phase 1: quantize source slab into q bytes ----
    constexpr int WPR = SC / 4;
    #pragma unroll 1
    for (int it = 0; it < (128 * WPR) / 256; it++) {
        int idx = tid + it * 256;
        int r = idx / WPR, wc = idx % WPR;
        float4 v;
        if (EPI == 1) {
            int m = m0 + r, j = wc * 4;
            if (j < FN) v = *(const float4*)(node + (m / NBRN) * FN + j);
            else        v = *(const float4*)(edge + (size_t)m * 64 + (j - 64));
        } else {
            v = *(const float4*)(g_h + (size_t)(m0 + r) * H1 + wc * 4);
        }
        unsigned p = qz(v.x, mn, mx) | (qz(v.y, mn, mx) << 8) |
                     (qz(v.z, mn, mx) << 16) | (qz(v.w, mn, mx) << 24);
        *(unsigned*)(qs + r * QROWB + wc * 4) = p;
    }
    __syncthreads();

    // ---- phase 1.5: bit-plane transpose q -> bitmaps ----
    constexpr int SEGS = SC / 16;
    #pragma unroll 1
    for (int t = tid; t < 128 * SEGS; t += 256) {
        int r = t / SEGS, seg = t % SEGS;
        unsigned long long x0 = *(const unsigned long long*)(qs + r * QROWB + seg * 16);
        unsigned long long x1 = *(const unsigned long long*)(qs + r * QROWB + seg * 16 + 8);
        #pragma unroll
        for (int b = 0; b < 8; b++) {
            unsigned short w16 = (unsigned short)(bits8(x0, b) | (bits8(x1, b) << 8));
            *(unsigned short*)(bp + (b * 128 + r) * BPR + seg * 2) = w16;
        }
    }

    // ---- k-loop ----
    float acc[2][8][4];
    #pragma unroll
    for (int a = 0; a < 2; a++)
        #pragma unroll
        for (int b = 0; b < 8; b++)
            #pragma unroll
            for (int c = 0; c < 4; c++) acc[a][b][c] = 0.f;

    auto loadB = [&](int s) {
        const __half* W; int rs, kofs;
        if (s < KTH) { W = Whi; rs = KHI; kofs = s * 64; }
        else         { W = Wlo; rs = KLO; kofs = (s - KTH) * 64; }
        __half* bs = bsm + (s % 3) * BTILE;
        #pragma unroll
        for (int it2 = 0; it2 < 4; it2++) {
            int cid = tid + it2 * 256;
            int r = cid >> 3, c = (cid & 7) * 8;
            cp_async16(&bs[r * SROW + c], W + (size_t)(n0 + r) * rs + kofs + c);
        }
        asm volatile("cp.async.commit_group;\n");
    };

    const int lm = lane >> 3, lr = lane & 7;
    const int lmbase = (wn * 64 + (lm >> 1) * 8 + lr) * SROW + (lm & 1) * 8;

    loadB(0);
    loadB(1);
    __syncthreads();
    #pragma unroll 1
    for (int s = 0; s < NST; s++) {
        if (s + 1 < NST) asm volatile("cp.async.wait_group 1;\n");
        else             asm volatile("cp.async.wait_group 0;\n");
        __syncthreads();
        if (s + 2 < NST) loadB(s + 2);

        // stage plane + byte window
        int b, i0;
        if (s < KTH) { b = s / SPP; i0 = (s % SPP) * 64; }
        else         { int s2 = s - KTH; b = 4 + s2 / SPP; i0 = (s2 % SPP) * 64; }
        int bofs = b * 128;

        // per-row 64-bit plane words, pre-shifted by lane k-offset
        unsigned long long wt0[2], wt8[2];
        #pragma unroll
        for (int mt = 0; mt < 2; mt++) {
            int r0 = wm * 32 + mt * 16 + g;
            wt0[mt] = (*(const unsigned long long*)(bp + (bofs + r0) * BPR + (i0 >> 3))) >> ti2;
            wt8[mt] = (*(const unsigned long long*)(bp + (bofs + r0 + 8) * BPR + (i0 >> 3))) >> ti2;
        }
        const __half* bs = bsm + (s % 3) * BTILE;

        #pragma unroll
        for (int kk = 0; kk < 4; kk++) {
            unsigned af[2][4];
            #pragma unroll
            for (int mt = 0; mt < 2; mt++) {
                unsigned lo0 = (unsigned)(wt0[mt] >> (kk * 16));
                unsigned lo1 = (unsigned)(wt8[mt] >> (kk * 16));
                af[mt][0] = (lo0 & 1u) * 0x3C00u | ((lo0 >> 1) & 1u) * 0x3C000000u;
                af[mt][1] = (lo1 & 1u) * 0x3C00u | ((lo1 >> 1) & 1u) * 0x3C000000u;
                af[mt][2] = ((lo0 >> 8) & 1u) * 0x3C00u | ((lo0 >> 9) & 1u) * 0x3C000000u;
                af[mt][3] = ((lo1 >> 8) & 1u) * 0x3C00u | ((lo1 >> 9) & 1u) * 0x3C000000u;
            }
            unsigned bq[8][2];
            #pragma unroll
            for (int p = 0; p < 4; p++)
                ldmx4(bq[2 * p][0], bq[2 * p][1], bq[2 * p + 1][0], bq[2 * p + 1][1],
                      bs + lmbase + p * (16 * SROW) + kk * 16);
            #pragma unroll
            for (int mt = 0; mt < 2; mt++)
                #pragma unroll
                for (int nt = 0; nt < 8; nt++)
                    asm volatile(
                        "mma.sync.aligned.m16n8k16.row.col.f32.f16.f16.f32 "
                        "{%0,%1,%2,%3},{%4,%5,%6,%7},{%8,%9},{%0,%1,%2,%3};"
                        : "+f"(acc[mt][nt][0]), "+f"(acc[mt][nt][1]),
                          "+f"(acc[mt][nt][2]), "+f"(acc[mt][nt][3])
                        : "r"(af[mt][0]), "r"(af[mt][1]), "r"(af[mt][2]), "r"(af[mt][3]),
                          "r"(bq[nt][0]), "r"(bq[nt][1]));
        }
    }

    // ---- epilogue ----
    float sc = (mx - mn) * (1.0f / 255.0f);
    if (EPI == 1) {
        float lmn = __int_as_float(0x7f800000), lmx = -lmn;
        #pragma unroll
        for (int mt = 0; mt < 2; mt++)
            #pragma unroll
            for (int nt = 0; nt < 8; nt++)
                #pragma unroll
                for (int c = 0; c < 4; c++) {
                    int row = m0 + wm * 32 + mt * 16 + g + ((c & 2) << 2);
                    int col = n0 + wn * 64 + nt * 8 + ti2 + (c & 1);
                    float hv = acc[mt][nt][c] * sc + mn * S[col];
                    hv = fmaxf(hv, 0.f);
                    out[(size_t)row * N + col] = hv;
                    lmn = fminf(lmn, hv); lmx = fmaxf(lmx, hv);
                }
        #pragma unroll
        for (int o = 16; o; o >>= 1) {
            lmn = fminf(lmn, __shfl_xor_sync(0xffffffffu, lmn, o));
            lmx = fmaxf(lmx, __shfl_xor_sync(0xffffffffu, lmx, o));
        }
        if (lane == 0) { atomicMinF(&g_mn2, lmn); atomicMaxF(&g_mx2, lmx); }
    } else {
        #pragma unroll
        for (int mt = 0; mt < 2; mt++)
            #pragma unroll
            for (int nt = 0; nt < 8; nt++)
                #pragma unroll
                for (int c = 0; c < 4; c++) {
                    int row = m0 + wm * 32 + mt * 16 + g + ((c & 2) << 2);
                    int col = n0 + wn * 64 + nt * 8 + ti2 + (c & 1);
                    out[(size_t)row * N + col] = acc[mt][nt][c] * sc + mn * S[col];
                }
    }
}

// sigmoid(gate)*tanh(extract)*mask, summed over 12 neighbors
__global__ void k_gate(const float* __restrict__ mask) {
    int idx = blockIdx.x * 256 + threadIdx.x;
    int ba = idx >> 6, j = idx & 63;
    float acc = 0.f;
    #pragma unroll
    for (int nb = 0; nb < NBRN; nb++) {
        int m = ba * NBRN + nb;
        float gv = g_c2[m * H2 + j];
        float ev = g_c2[m * H2 + 64 + j];
        acc += (1.f / (1.f + expf(-gv))) * tanhf(ev) * mask[m];
    }
    g_ns[idx] = acc;
}

// deterministic per-feature BN statistics
__global__ void k_stats() {
    int j = blockIdx.x, t = threadIdx.x;
    __shared__ float red[256];
    __shared__ float mean_s;
    float s = 0.f;
    for (int r = t; r < BA_ROWS; r += 256) s += g_ns[r * FN + j];
    red[t] = s; __syncthreads();
    #pragma unroll
    for (int k = 128; k; k >>= 1) { if (t < k) red[t] += red[t + k]; __syncthreads(); }
    if (t == 0) mean_s = red[0] / (float)BA_ROWS;
    __syncthreads();
    float mean = mean_s, s2 = 0.f;
    for (int r = t; r < BA_ROWS; r += 256) { float d = g_ns[r * FN + j] - mean; s2 += d * d; }
    red[t] = s2; __syncthreads();
    #pragma unroll
    for (int k = 128; k; k >>= 1) { if (t < k) red[t] += red[t + k]; __syncthreads(); }
    if (t == 0) { g_mean[j] = mean; g_var[j] = red[0] / (float)BA_ROWS; }
}

__global__ void k_final(const float* __restrict__ node, const float* __restrict__ gamma,
                        const float* __restrict__ beta, float* __restrict__ out) {
    int idx = blockIdx.x * 256 + threadIdx.x;
    int j = idx & 63;
    float bn = (g_ns[idx] - g_mean[j]) / sqrtf(g_var[j] + 1e-5f) * gamma[j] + beta[j];
    out[idx] = fmaxf(node[idx] + bn, 0.f);
}

// ---------------- launcher ----------------
extern "C" void kernel_launch(void* const* d_in, const int* in_sizes, int n_in,
                              void* d_out, int out_size) {
    const float* node  = (const float*)d_in[0];
    const float* edge  = (const float*)d_in[1];
    const float* maskp = (const float*)d_in[2];
    const float* cond1 = (const float*)d_in[3];
    const float* cond2 = (const float*)d_in[4];
    const float* eps1  = (const float*)d_in[5];
    const float* eps2  = (const float*)d_in[6];
    const float* gamma = (const float*)d_in[7];
    const float* beta  = (const float*)d_in[8];
    float* out = (float*)d_out;

    // smem: 3 B tiles + bitmaps + q slab
    const int SMEM1 = 3 * 128 * 72 * 2 + 8 * 128 * (F1 / 8 + 8) + 128 * (F1 + 16);  // 98304
    const int SMEM2 = 3 * 128 * 72 * 2 + 8 * 128 * (H1 / 8 + 8) + 128 * (H1 + 16);  // 196608
    cudaFuncSetAttribute(k_tc<1>, cudaFuncAttributeMaxDynamicSharedMemorySize, SMEM1);
    cudaFuncSetAttribute(k_tc<2>, cudaFuncAttributeMaxDynamicSharedMemorySize, SMEM2);

    k_init<<<1, 1>>>();
    k_minmax<<<(NODE_N + EDGE_N) / 256, 256>>>(node, edge);
    k_prep1<<<H1, 128>>>(cond1, eps1);
    k_prep2<<<H2, 256>>>(cond2, eps2);
    k_tc<1><<<dim3(H1 / 128, M_ROWS / 128), 256, SMEM1>>>(node, edge);
    k_tc<2><<<dim3(1, M_ROWS / 128), 256, SMEM2>>>(nullptr, nullptr);
    k_gate<<<(BA_ROWS * FN) / 256, 256>>>(maskp);
    k_stats<<<FN, 256>>>();
    k_final<<<(BA_ROWS * FN) / 256, 256>>>(node, gamma, beta, out);
}